// round 7
// baseline (speedup 1.0000x reference)
#include <cuda_runtime.h>
#include <cuda_bf16.h>
#include <math.h>
#include <stdint.h>

#define BB   256
#define TT   365
#define HH   512
#define DD   32
#define K3   1536
#define DS   27
#define NBLK 128
#define KTOT 544

// ---------------- persistent device state ----------------
// Weight staging: row P = nt*96 + g*32 + ul, k in [0,544) = [x(32) ; h(512)]
__device__ __align__(16) __nv_bfloat16 g_Wp_hi[K3 * KTOT];
__device__ __align__(16) __nv_bfloat16 g_Wp_lo[K3 * KTOT];
__device__ __align__(16) __nv_bfloat16 g_x_hi[BB * TT * DD];
__device__ __align__(16) __nv_bfloat16 g_x_lo[BB * TT * DD];
__device__ __align__(16) __nv_bfloat16 g_h_hi[2][BB * HH];
__device__ __align__(16) __nv_bfloat16 g_h_lo[2][BB * HH];

__device__ __forceinline__ float hsig(float x) {
    return fminf(fmaxf(0.2f * x + 0.5f, 0.0f), 1.0f);
}
__device__ __forceinline__ float ftanh(float x) {
    float t = __expf(-2.0f * fabsf(x));
    return copysignf(__fdividef(1.0f - t, 1.0f + t), x);
}
__device__ __forceinline__ uint32_t smem_u32(const void* p) {
    uint32_t a;
    asm("{ .reg .u64 t; cvta.to.shared.u64 t, %1; cvt.u32.u64 %0, t; }" : "=r"(a) : "l"(p));
    return a;
}

#define LDSM_X4(r0, r1, r2, r3, addr)                                          \
    asm volatile("ldmatrix.sync.aligned.m8n8.x4.shared.b16 {%0,%1,%2,%3}, [%4];" \
                 : "=r"(r0), "=r"(r1), "=r"(r2), "=r"(r3) : "r"(addr))

#define MMA_BF16(d, a0, a1, a2, a3, b0, b1)                                    \
    asm volatile("mma.sync.aligned.m16n8k16.row.col.f32.bf16.bf16.f32 "        \
                 "{%0,%1,%2,%3}, {%4,%5,%6,%7}, {%8,%9}, {%0,%1,%2,%3};"       \
                 : "+f"((d)[0]), "+f"((d)[1]), "+f"((d)[2]), "+f"((d)[3])      \
                 : "r"(a0), "r"(a1), "r"(a2), "r"(a3), "r"(b0), "r"(b1))

#define CP_ASYNC(dst, src, sz) \
    asm volatile("cp.async.cg.shared.global [%0], [%1], 16, %2;" \
                 :: "r"(dst), "l"(src), "r"(sz))
#define CP_COMMIT() asm volatile("cp.async.commit_group;" ::: "memory")
#define CP_WAIT0()  asm volatile("cp.async.wait_group 0;" ::: "memory")
#define CP_WAIT1()  asm volatile("cp.async.wait_group 1;" ::: "memory")

#define CLUSTER_ARRIVE() asm volatile("barrier.cluster.arrive.aligned;" ::: "memory")
#define CLUSTER_WAIT()   asm volatile("barrier.cluster.wait.aligned;" ::: "memory")

// ---------------- SMEM layout ----------------
#define BROW      1104            // 544*2 + 16B pad
#define SM_BHI    0
#define SM_BLO    105984
#define SM_A      211968          // 2 bufs x (hi 4608 + lo 4608); also reduction area
#define ABUF_SZ   9216
#define SMEM_TOTAL 230400

// ---------------- prep kernels ----------------
__global__ void prep_weights(const float* __restrict__ Wx, const float* __restrict__ Wh) {
    int P = blockIdx.x;                 // P = nt*96 + g*32 + ul
    int nt = P / 96, rq = P - nt * 96;
    int g = rq >> 5, ul = rq & 31;
    int col = g * HH + nt * 32 + ul;
    for (int k = threadIdx.x; k < KTOT; k += blockDim.x) {
        float w = (k < DD) ? Wx[(size_t)k * K3 + col]
                           : Wh[(size_t)(k - DD) * K3 + col];
        __nv_bfloat16 hi = __float2bfloat16(w);
        g_Wp_hi[(size_t)P * KTOT + k] = hi;
        g_Wp_lo[(size_t)P * KTOT + k] = __float2bfloat16(w - __bfloat162float(hi));
    }
}

__global__ void prep_x(const float* __restrict__ x_dyn) {
    int i = blockIdx.x * blockDim.x + threadIdx.x;
    if (i >= BB * TT * DD) return;
    float v = x_dyn[i];
    __nv_bfloat16 hi = __float2bfloat16(v);
    g_x_hi[i] = hi;
    g_x_lo[i] = __float2bfloat16(v - __bfloat162float(hi));
}

// ---------------- A-chunk loader (256 threads) ----------------
__device__ __forceinline__ void issue_chunk(int j, int t, int m0, uint32_t abase,
                                            const __nv_bfloat16* __restrict__ hhi,
                                            const __nv_bfloat16* __restrict__ hlo,
                                            int tid) {
#pragma unroll
    for (int n = 0; n < 2; n++) {
        int i = tid + n * 256;
        int half = i >> 8;              // 0 hi, 1 lo
        int rem = i & 255;
        int rr = rem >> 3, q = rem & 7;
        uint32_t dst = abase + half * 4608 + rr * 144 + q * 16;
        const __nv_bfloat16* hb = half ? hlo : hhi;
        const __nv_bfloat16* src;
        int sz = 16;
        if (j == 0) {
            if (q < 4) src = (half ? g_x_lo : g_x_hi) + ((size_t)(m0 + rr) * TT + t) * DD + q * 8;
            else       src = hb + (size_t)(m0 + rr) * HH + (q - 4) * 8;
        } else if (j < 8) {
            src = hb + (size_t)(m0 + rr) * HH + 64 * j - 32 + q * 8;
        } else {
            src = hb + (size_t)(m0 + rr) * HH + 480 + (q & 3) * 8;
            if (q >= 4) sz = 0;
        }
        CP_ASYNC(dst, src, sz);
    }
    CP_COMMIT();
}

// ---------------- persistent LSTM kernel ----------------
// 128 CTAs (8 clusters of 16) x 256 thr. CTA tile 32 rows x 32 units.
// Warp tile 32m x 8u x 3g; warps w and w+4 split the k-dim, reduced at end.
__global__ __launch_bounds__(256, 1) __cluster_dims__(16, 1, 1)
void lstm_persist(const float* __restrict__ x_static,
                  const float* __restrict__ sk,
                  const float* __restrict__ sb,
                  const float* __restrict__ bias,
                  float* __restrict__ out) {
    extern __shared__ char smem[];
    const uint32_t s0 = smem_u32(smem);
    const int tid = threadIdx.x;
    const int lane = tid & 31;
    const int wid = tid >> 5;
    const int nq = wid & 3;             // 8-unit span
    const int khalf = wid >> 2;         // 0: ks {0,1}, 1: ks {2,3}
    const int mt = blockIdx.x >> 4;     // cluster id
    const int nt = blockIdx.x & 15;     // rank within cluster
    const int m0 = mt * 32;
    const int u0 = nt * 32;

    // ---- one-time: weights into SMEM ----
    for (int i = tid; i < 96 * 68; i += 256) {
        int pl = i / 68, c = i - pl * 68;
        size_t src = (size_t)(nt * 96 + pl) * KTOT + c * 8;
        *reinterpret_cast<uint4*>(smem + SM_BHI + pl * BROW + c * 16) =
            *reinterpret_cast<const uint4*>(&g_Wp_hi[src]);
        *reinterpret_cast<uint4*>(smem + SM_BLO + pl * BROW + c * 16) =
            *reinterpret_cast<const uint4*>(&g_Wp_lo[src]);
    }

    // ---- per-thread ownership (epilogue warps 0-3 only):
    // rows m0 + (lane>>2) + {0,8,16,24}, units uA, uA+1
    const int gr = m0 + (lane >> 2);
    const int uA = u0 + nq * 8 + (lane & 3) * 2;

    const float bf0 = bias[uA],          bf1 = bias[uA + 1];
    const float bg0 = bias[HH + uA],     bg1 = bias[HH + uA + 1];
    const float bo0 = bias[2 * HH + uA], bo1 = bias[2 * HH + uA + 1];

    float c_reg[8], ig_reg[8];
#pragma unroll
    for (int i = 0; i < 8; i++) c_reg[i] = 0.f;
    if (khalf == 0) {
#pragma unroll
        for (int i = 0; i < 4; i++) {
            int row = gr + i * 8;
#pragma unroll
            for (int jj = 0; jj < 2; jj++) {
                int u = uA + jj;
                float a = sb[u];
#pragma unroll
                for (int d = 0; d < DS; d++)
                    a = fmaf(x_static[row * DS + d], sk[d * HH + u], a);
                ig_reg[i * 2 + jj] = hsig(a);
            }
            __nv_bfloat162 z2; z2.x = __float2bfloat16(0.f); z2.y = z2.x;
            *reinterpret_cast<__nv_bfloat162*>(&g_h_hi[0][row * HH + uA]) = z2;
            *reinterpret_cast<__nv_bfloat162*>(&g_h_lo[0][row * HH + uA]) = z2;
        }
    }
    __syncthreads();
    CLUSTER_ARRIVE();
    CLUSTER_WAIT();

    // ---- ldmatrix lane addresses ----
    // A (32 rows x k): frag0 rows 0-15, frag1 rows 16-31
    const uint32_t a_off = (lane & 15) * 144 + (lane >> 4) * 16;
    const int oct = lane >> 3, l8 = lane & 7;
    const uint32_t koff = (oct & 1) * 16;
    const int wq8 = nq * 8;
    // X4 #1: [f_hi k0, f_hi k8, g_hi k0, g_hi k8]
    const uint32_t bA = s0 + SM_BHI + ((oct < 2 ? wq8 : 32 + wq8) + l8) * BROW + koff;
    // X4 #2: [o_hi k0, o_hi k8, f_lo k0, f_lo k8]
    const uint32_t bB = (oct < 2 ? s0 + SM_BHI + (64 + wq8 + l8) * BROW
                                 : s0 + SM_BLO + (wq8 + l8) * BROW) + koff;
    // X4 #3: [g_lo k0, g_lo k8, o_lo k0, o_lo k8]
    const uint32_t bC = s0 + SM_BLO + ((oct < 2 ? 32 : 64) + wq8 + l8) * BROW + koff;

#pragma unroll 1
    for (int t = 0; t < TT; t++) {
        const int tpar = t & 1;
        const __nv_bfloat16* __restrict__ hhi = g_h_hi[tpar];
        const __nv_bfloat16* __restrict__ hlo = g_h_lo[tpar];

        float acc[3][2][4];                  // [gate][mfrag][elem]
#pragma unroll
        for (int g = 0; g < 3; g++)
#pragma unroll
            for (int mf = 0; mf < 2; mf++)
#pragma unroll
                for (int e = 0; e < 4; e++) acc[g][mf][e] = 0.f;

        issue_chunk(0, t, m0, s0 + SM_A, hhi, hlo, tid);

#pragma unroll 1
        for (int j = 0; j < 9; j++) {
            if (j > 0) __syncthreads();
            if (j < 8) {
                issue_chunk(j + 1, t, m0, s0 + SM_A + ((j + 1) & 1) * ABUF_SZ, hhi, hlo, tid);
                CP_WAIT1();
            } else {
                CP_WAIT0();
            }
            __syncthreads();

            const uint32_t Abase = s0 + SM_A + (j & 1) * ABUF_SZ + a_off;
            const uint32_t Bk = j * 128;
            const int ks0 = (j < 8) ? khalf * 2 : khalf;
            const int nks = (j < 8) ? 2 : 1;

            for (int ii = 0; ii < nks; ii++) {
                const int ks = ks0 + ii;
                uint32_t ah0, ah1, ah2, ah3, ai0, ai1, ai2, ai3;   // hi frag0, frag1
                uint32_t al0, al1, al2, al3, am0, am1, am2, am3;   // lo frag0, frag1
                uint32_t p0, p1, p2, p3, q0, q1, q2, q3, r0, r1, r2, r3;
                LDSM_X4(ah0, ah1, ah2, ah3, Abase + ks * 32);
                LDSM_X4(ai0, ai1, ai2, ai3, Abase + 16 * 144 + ks * 32);
                LDSM_X4(al0, al1, al2, al3, Abase + 4608 + ks * 32);
                LDSM_X4(am0, am1, am2, am3, Abase + 4608 + 16 * 144 + ks * 32);
                LDSM_X4(p0, p1, p2, p3, bA + Bk + ks * 32);
                LDSM_X4(q0, q1, q2, q3, bB + Bk + ks * 32);
                LDSM_X4(r0, r1, r2, r3, bC + Bk + ks * 32);
                // hi x hi
                MMA_BF16(acc[0][0], ah0, ah1, ah2, ah3, p0, p1);
                MMA_BF16(acc[0][1], ai0, ai1, ai2, ai3, p0, p1);
                MMA_BF16(acc[1][0], ah0, ah1, ah2, ah3, p2, p3);
                MMA_BF16(acc[1][1], ai0, ai1, ai2, ai3, p2, p3);
                MMA_BF16(acc[2][0], ah0, ah1, ah2, ah3, q0, q1);
                MMA_BF16(acc[2][1], ai0, ai1, ai2, ai3, q0, q1);
                // hi x lo (weights lo)
                MMA_BF16(acc[0][0], ah0, ah1, ah2, ah3, q2, q3);
                MMA_BF16(acc[0][1], ai0, ai1, ai2, ai3, q2, q3);
                MMA_BF16(acc[1][0], ah0, ah1, ah2, ah3, r0, r1);
                MMA_BF16(acc[1][1], ai0, ai1, ai2, ai3, r0, r1);
                MMA_BF16(acc[2][0], ah0, ah1, ah2, ah3, r2, r3);
                MMA_BF16(acc[2][1], ai0, ai1, ai2, ai3, r2, r3);
                // lo x hi (activations lo)
                MMA_BF16(acc[0][0], al0, al1, al2, al3, p0, p1);
                MMA_BF16(acc[0][1], am0, am1, am2, am3, p0, p1);
                MMA_BF16(acc[1][0], al0, al1, al2, al3, p2, p3);
                MMA_BF16(acc[1][1], am0, am1, am2, am3, p2, p3);
                MMA_BF16(acc[2][0], al0, al1, al2, al3, q0, q1);
                MMA_BF16(acc[2][1], am0, am1, am2, am3, q0, q1);
            }
        }

        // ---- cross-warp k reduction via smem (A staging is free now) ----
        __syncthreads();
        float* red = reinterpret_cast<float*>(smem + SM_A);
        if (khalf == 1) {
            int s = (wid - 4) * 32 + lane;
#pragma unroll
            for (int g = 0; g < 3; g++)
#pragma unroll
                for (int mf = 0; mf < 2; mf++)
#pragma unroll
                    for (int e = 0; e < 4; e++)
                        red[(g * 8 + mf * 4 + e) * 128 + s] = acc[g][mf][e];
        }
        __syncthreads();

        if (khalf == 0) {
            int s = wid * 32 + lane;
#pragma unroll
            for (int g = 0; g < 3; g++)
#pragma unroll
                for (int mf = 0; mf < 2; mf++)
#pragma unroll
                    for (int e = 0; e < 4; e++)
                        acc[g][mf][e] += red[(g * 8 + mf * 4 + e) * 128 + s];

            __nv_bfloat16* __restrict__ hdst_hi = g_h_hi[tpar ^ 1];
            __nv_bfloat16* __restrict__ hdst_lo = g_h_lo[tpar ^ 1];
#pragma unroll
            for (int i = 0; i < 4; i++) {           // row gr + i*8
                const int mf = i >> 1, dp = (i & 1) * 2;
                float zf0 = acc[0][mf][dp + 0] + bf0, zf1 = acc[0][mf][dp + 1] + bf1;
                float zg0 = acc[1][mf][dp + 0] + bg0, zg1 = acc[1][mf][dp + 1] + bg1;
                float zo0 = acc[2][mf][dp + 0] + bo0, zo1 = acc[2][mf][dp + 1] + bo1;
                float c0 = hsig(zf0) * c_reg[i * 2 + 0] + ig_reg[i * 2 + 0] * ftanh(zg0);
                float c1 = hsig(zf1) * c_reg[i * 2 + 1] + ig_reg[i * 2 + 1] * ftanh(zg1);
                c_reg[i * 2 + 0] = c0;
                c_reg[i * 2 + 1] = c1;
                float h0 = hsig(zo0) * ftanh(c0);
                float h1 = hsig(zo1) * ftanh(c1);
                int row = gr + i * 8;
                int idx = row * HH + uA;
                __nv_bfloat16 b0 = __float2bfloat16(h0);
                __nv_bfloat16 b1 = __float2bfloat16(h1);
                __nv_bfloat162 ph; ph.x = b0; ph.y = b1;
                *reinterpret_cast<__nv_bfloat162*>(&hdst_hi[idx]) = ph;
                __nv_bfloat162 pl;
                pl.x = __float2bfloat16(h0 - __bfloat162float(b0));
                pl.y = __float2bfloat16(h1 - __bfloat162float(b1));
                *reinterpret_cast<__nv_bfloat162*>(&hdst_lo[idx]) = pl;
                float2 ov = make_float2(h0, h1);
                *reinterpret_cast<float2*>(&out[(size_t)row * TT * HH + (size_t)t * HH + uA]) = ov;
            }
        }

        CLUSTER_ARRIVE();
        CLUSTER_WAIT();
    }
}

// ---------------- launcher ----------------
extern "C" void kernel_launch(void* const* d_in, const int* in_sizes, int n_in,
                              void* d_out, int out_size) {
    const float* x_dyn    = (const float*)d_in[0];
    const float* x_static = (const float*)d_in[1];
    const float* Wx       = (const float*)d_in[2];
    const float* Wh       = (const float*)d_in[3];
    const float* bias     = (const float*)d_in[4];
    const float* sk       = (const float*)d_in[5];
    const float* sb       = (const float*)d_in[6];
    float* out = (float*)d_out;

    cudaFuncSetAttribute(lstm_persist, cudaFuncAttributeMaxDynamicSharedMemorySize, SMEM_TOTAL);
    cudaFuncSetAttribute(lstm_persist, cudaFuncAttributeNonPortableClusterSizeAllowed, 1);

    prep_weights<<<K3, 128>>>(Wx, Wh);
    prep_x<<<(BB * TT * DD + 127) / 128, 128>>>(x_dyn);
    lstm_persist<<<NBLK, 256, SMEM_TOTAL>>>(x_static, sk, sb, bias, out);
}

// round 8
// speedup vs baseline: 1.8278x; 1.8278x over previous
#include <cuda_runtime.h>
#include <cuda_bf16.h>
#include <math.h>
#include <stdint.h>

#define BB   256
#define TT   365
#define HH   512
#define DD   32
#define K3   1536
#define DS   27
#define NBLK 128
#define KTOT 544

// ---------------- persistent device state ----------------
// Weight staging: row P = nt*96 + g*32 + ul, k in [0,544) = [x(32) ; h(512)]
__device__ __align__(16) __nv_bfloat16 g_Wp_hi[K3 * KTOT];
__device__ __align__(16) __nv_bfloat16 g_Wp_lo[K3 * KTOT];
__device__ __align__(16) __nv_bfloat16 g_x_hi[BB * TT * DD];
__device__ __align__(16) __nv_bfloat16 g_x_lo[BB * TT * DD];
__device__ __align__(16) __nv_bfloat16 g_h_hi[2][BB * HH];
__device__ __align__(16) __nv_bfloat16 g_h_lo[2][BB * HH];
__device__ unsigned g_grp_cnt[8 * 32];      // 128B stride per mt-group
__device__ unsigned g_grp_phase[8 * 32];

__device__ __forceinline__ float hsig(float x) {
    return fminf(fmaxf(0.2f * x + 0.5f, 0.0f), 1.0f);
}
__device__ __forceinline__ float ftanh(float x) {
    float t = __expf(-2.0f * fabsf(x));
    return copysignf(__fdividef(1.0f - t, 1.0f + t), x);
}
__device__ __forceinline__ uint32_t smem_u32(const void* p) {
    uint32_t a;
    asm("{ .reg .u64 t; cvta.to.shared.u64 t, %1; cvt.u32.u64 %0, t; }" : "=r"(a) : "l"(p));
    return a;
}

#define LDSM_X4(r0, r1, r2, r3, addr)                                          \
    asm volatile("ldmatrix.sync.aligned.m8n8.x4.shared.b16 {%0,%1,%2,%3}, [%4];" \
                 : "=r"(r0), "=r"(r1), "=r"(r2), "=r"(r3) : "r"(addr))

#define MMA_BF16(d, a0, a1, a2, a3, b0, b1)                                    \
    asm volatile("mma.sync.aligned.m16n8k16.row.col.f32.bf16.bf16.f32 "        \
                 "{%0,%1,%2,%3}, {%4,%5,%6,%7}, {%8,%9}, {%0,%1,%2,%3};"       \
                 : "+f"((d)[0]), "+f"((d)[1]), "+f"((d)[2]), "+f"((d)[3])      \
                 : "r"(a0), "r"(a1), "r"(a2), "r"(a3), "r"(b0), "r"(b1))

#define CP_ASYNC(dst, src, sz) \
    asm volatile("cp.async.cg.shared.global [%0], [%1], 16, %2;" \
                 :: "r"(dst), "l"(src), "r"(sz))
#define CP_COMMIT() asm volatile("cp.async.commit_group;" ::: "memory")
#define CP_WAIT0()  asm volatile("cp.async.wait_group 0;" ::: "memory")
#define CP_WAIT1()  asm volatile("cp.async.wait_group 1;" ::: "memory")

// ---------------- SMEM layout ----------------
#define BROW      1104            // 544*2 + 16B pad
#define SM_BHI    0
#define SM_BLO    105984
#define SM_A      211968          // 2 bufs x (hi 4608 + lo 4608); also reduction area
#define ABUF_SZ   9216
#define SMEM_TOTAL 230400

// ---------------- prep kernels ----------------
__global__ void reset_bar() {
    if (threadIdx.x < 8 * 32) {
        g_grp_cnt[threadIdx.x] = 0;
        g_grp_phase[threadIdx.x] = 0;
    }
}

__global__ void prep_weights(const float* __restrict__ Wx, const float* __restrict__ Wh) {
    int P = blockIdx.x;                 // P = nt*96 + g*32 + ul
    int nt = P / 96, rq = P - nt * 96;
    int g = rq >> 5, ul = rq & 31;
    int col = g * HH + nt * 32 + ul;
    for (int k = threadIdx.x; k < KTOT; k += blockDim.x) {
        float w = (k < DD) ? Wx[(size_t)k * K3 + col]
                           : Wh[(size_t)(k - DD) * K3 + col];
        __nv_bfloat16 hi = __float2bfloat16(w);
        g_Wp_hi[(size_t)P * KTOT + k] = hi;
        g_Wp_lo[(size_t)P * KTOT + k] = __float2bfloat16(w - __bfloat162float(hi));
    }
}

__global__ void prep_x(const float* __restrict__ x_dyn) {
    int i = blockIdx.x * blockDim.x + threadIdx.x;
    if (i >= BB * TT * DD) return;
    float v = x_dyn[i];
    __nv_bfloat16 hi = __float2bfloat16(v);
    g_x_hi[i] = hi;
    g_x_lo[i] = __float2bfloat16(v - __bfloat162float(hi));
}

// ---------------- group barrier: 16 CTAs sharing mt (release/acquire) ------
__device__ __forceinline__ void grid_bar_grp(int mt, unsigned target) {
    __syncthreads();
    if (threadIdx.x == 0) {
        unsigned old;
        asm volatile("atom.add.acq_rel.gpu.global.u32 %0, [%1], 1;"
                     : "=r"(old) : "l"(&g_grp_cnt[mt * 32]) : "memory");
        if (old + 1u == target * 16u) {
            asm volatile("st.release.gpu.global.u32 [%0], %1;"
                         :: "l"(&g_grp_phase[mt * 32]), "r"(target) : "memory");
        } else {
            unsigned p;
            do {
                asm volatile("ld.acquire.gpu.global.u32 %0, [%1];"
                             : "=r"(p) : "l"(&g_grp_phase[mt * 32]) : "memory");
            } while (p < target);
        }
    }
    __syncthreads();
}

// ---------------- A-chunk loader (256 threads) ----------------
__device__ __forceinline__ void issue_chunk(int j, int t, int m0, uint32_t abase,
                                            const __nv_bfloat16* __restrict__ hhi,
                                            const __nv_bfloat16* __restrict__ hlo,
                                            int tid) {
#pragma unroll
    for (int n = 0; n < 2; n++) {
        int i = tid + n * 256;
        int half = i >> 8;              // 0 hi, 1 lo
        int rem = i & 255;
        int rr = rem >> 3, q = rem & 7;
        uint32_t dst = abase + half * 4608 + rr * 144 + q * 16;
        const __nv_bfloat16* hb = half ? hlo : hhi;
        const __nv_bfloat16* src;
        int sz = 16;
        if (j == 0) {
            if (q < 4) src = (half ? g_x_lo : g_x_hi) + ((size_t)(m0 + rr) * TT + t) * DD + q * 8;
            else       src = hb + (size_t)(m0 + rr) * HH + (q - 4) * 8;
        } else if (j < 8) {
            src = hb + (size_t)(m0 + rr) * HH + 64 * j - 32 + q * 8;
        } else {
            src = hb + (size_t)(m0 + rr) * HH + 480 + (q & 3) * 8;
            if (q >= 4) sz = 0;
        }
        CP_ASYNC(dst, src, sz);
    }
    CP_COMMIT();
}

// ---------------- persistent LSTM kernel ----------------
// 128 CTAs x 256 thr. CTA tile 32 rows x 32 units (96 z-cols).
// Warp tile 32m x 8u x 3g; warps w and w+4 split the k-dim, reduced via smem.
__global__ __launch_bounds__(256, 1)
void lstm_persist(const float* __restrict__ x_static,
                  const float* __restrict__ sk,
                  const float* __restrict__ sb,
                  const float* __restrict__ bias,
                  float* __restrict__ out) {
    extern __shared__ char smem[];
    const uint32_t s0 = smem_u32(smem);
    const int tid = threadIdx.x;
    const int lane = tid & 31;
    const int wid = tid >> 5;
    const int nq = wid & 3;             // 8-unit span
    const int khalf = wid >> 2;         // 0: first ks half, 1: second
    const int mt = blockIdx.x & 7;
    const int nt = blockIdx.x >> 3;
    const int m0 = mt * 32;
    const int u0 = nt * 32;

    // ---- one-time: weights into SMEM ----
    for (int i = tid; i < 96 * 68; i += 256) {
        int pl = i / 68, c = i - pl * 68;
        size_t src = (size_t)(nt * 96 + pl) * KTOT + c * 8;
        *reinterpret_cast<uint4*>(smem + SM_BHI + pl * BROW + c * 16) =
            *reinterpret_cast<const uint4*>(&g_Wp_hi[src]);
        *reinterpret_cast<uint4*>(smem + SM_BLO + pl * BROW + c * 16) =
            *reinterpret_cast<const uint4*>(&g_Wp_lo[src]);
    }

    // ---- per-thread ownership (epilogue lives in khalf==0 warps):
    // rows gr + {0,8,16,24}, units uA, uA+1
    const int gr = m0 + (lane >> 2);
    const int uA = u0 + nq * 8 + (lane & 3) * 2;

    const float bf0 = bias[uA],          bf1 = bias[uA + 1];
    const float bg0 = bias[HH + uA],     bg1 = bias[HH + uA + 1];
    const float bo0 = bias[2 * HH + uA], bo1 = bias[2 * HH + uA + 1];

    float c_reg[8], ig_reg[8];
#pragma unroll
    for (int i = 0; i < 8; i++) c_reg[i] = 0.f;
    if (khalf == 0) {
#pragma unroll
        for (int i = 0; i < 4; i++) {
            int row = gr + i * 8;
#pragma unroll
            for (int jj = 0; jj < 2; jj++) {
                int u = uA + jj;
                float a = sb[u];
#pragma unroll
                for (int d = 0; d < DS; d++)
                    a = fmaf(x_static[row * DS + d], sk[d * HH + u], a);
                ig_reg[i * 2 + jj] = hsig(a);
            }
            __nv_bfloat162 z2; z2.x = __float2bfloat16(0.f); z2.y = z2.x;
            *reinterpret_cast<__nv_bfloat162*>(&g_h_hi[0][row * HH + uA]) = z2;
            *reinterpret_cast<__nv_bfloat162*>(&g_h_lo[0][row * HH + uA]) = z2;
        }
    }

    unsigned bar_t = 1;
    grid_bar_grp(mt, bar_t++);

    // ---- ldmatrix lane addresses ----
    const uint32_t a_off = (lane & 15) * 144 + (lane >> 4) * 16;
    const int oct = lane >> 3, l8 = lane & 7;
    const uint32_t koff = (oct & 1) * 16;
    const int wq8 = nq * 8;
    // X4 #1: [f_hi k0, f_hi k8, g_hi k0, g_hi k8]
    const uint32_t bA = s0 + SM_BHI + ((oct < 2 ? wq8 : 32 + wq8) + l8) * BROW + koff;
    // X4 #2: [o_hi k0, o_hi k8, f_lo k0, f_lo k8]
    const uint32_t bB = (oct < 2 ? s0 + SM_BHI + (64 + wq8 + l8) * BROW
                                 : s0 + SM_BLO + (wq8 + l8) * BROW) + koff;
    // X4 #3: [g_lo k0, g_lo k8, o_lo k0, o_lo k8]
    const uint32_t bC = s0 + SM_BLO + ((oct < 2 ? 32 : 64) + wq8 + l8) * BROW + koff;

#pragma unroll 1
    for (int t = 0; t < TT; t++) {
        const int tpar = t & 1;
        const __nv_bfloat16* __restrict__ hhi = g_h_hi[tpar];
        const __nv_bfloat16* __restrict__ hlo = g_h_lo[tpar];

        float acc[3][2][4];                  // [gate][mfrag][elem]
#pragma unroll
        for (int g = 0; g < 3; g++)
#pragma unroll
            for (int mf = 0; mf < 2; mf++)
#pragma unroll
                for (int e = 0; e < 4; e++) acc[g][mf][e] = 0.f;

        issue_chunk(0, t, m0, s0 + SM_A, hhi, hlo, tid);

#pragma unroll 1
        for (int j = 0; j < 9; j++) {
            if (j > 0) __syncthreads();
            if (j < 8) {
                issue_chunk(j + 1, t, m0, s0 + SM_A + ((j + 1) & 1) * ABUF_SZ, hhi, hlo, tid);
                CP_WAIT1();
            } else {
                CP_WAIT0();
            }
            __syncthreads();

            const uint32_t Abase = s0 + SM_A + (j & 1) * ABUF_SZ + a_off;
            const uint32_t Bk = j * 128;
            const int ks0 = (j < 8) ? khalf * 2 : khalf;
            const int nks = (j < 8) ? 2 : 1;

            for (int ii = 0; ii < nks; ii++) {
                const int ks = ks0 + ii;
                uint32_t ah0, ah1, ah2, ah3, ai0, ai1, ai2, ai3;   // hi frag0, frag1
                uint32_t al0, al1, al2, al3, am0, am1, am2, am3;   // lo frag0, frag1
                uint32_t p0, p1, p2, p3, q0, q1, q2, q3, r0, r1, r2, r3;
                LDSM_X4(ah0, ah1, ah2, ah3, Abase + ks * 32);
                LDSM_X4(ai0, ai1, ai2, ai3, Abase + 16 * 144 + ks * 32);
                LDSM_X4(al0, al1, al2, al3, Abase + 4608 + ks * 32);
                LDSM_X4(am0, am1, am2, am3, Abase + 4608 + 16 * 144 + ks * 32);
                LDSM_X4(p0, p1, p2, p3, bA + Bk + ks * 32);
                LDSM_X4(q0, q1, q2, q3, bB + Bk + ks * 32);
                LDSM_X4(r0, r1, r2, r3, bC + Bk + ks * 32);
                // hi x hi
                MMA_BF16(acc[0][0], ah0, ah1, ah2, ah3, p0, p1);
                MMA_BF16(acc[0][1], ai0, ai1, ai2, ai3, p0, p1);
                MMA_BF16(acc[1][0], ah0, ah1, ah2, ah3, p2, p3);
                MMA_BF16(acc[1][1], ai0, ai1, ai2, ai3, p2, p3);
                MMA_BF16(acc[2][0], ah0, ah1, ah2, ah3, q0, q1);
                MMA_BF16(acc[2][1], ai0, ai1, ai2, ai3, q0, q1);
                // hi x lo (weight lo)
                MMA_BF16(acc[0][0], ah0, ah1, ah2, ah3, q2, q3);
                MMA_BF16(acc[0][1], ai0, ai1, ai2, ai3, q2, q3);
                MMA_BF16(acc[1][0], ah0, ah1, ah2, ah3, r0, r1);
                MMA_BF16(acc[1][1], ai0, ai1, ai2, ai3, r0, r1);
                MMA_BF16(acc[2][0], ah0, ah1, ah2, ah3, r2, r3);
                MMA_BF16(acc[2][1], ai0, ai1, ai2, ai3, r2, r3);
                // lo x hi (activation lo)
                MMA_BF16(acc[0][0], al0, al1, al2, al3, p0, p1);
                MMA_BF16(acc[0][1], am0, am1, am2, am3, p0, p1);
                MMA_BF16(acc[1][0], al0, al1, al2, al3, p2, p3);
                MMA_BF16(acc[1][1], am0, am1, am2, am3, p2, p3);
                MMA_BF16(acc[2][0], al0, al1, al2, al3, q0, q1);
                MMA_BF16(acc[2][1], am0, am1, am2, am3, q0, q1);
            }
        }

        // ---- cross-warp k reduction via smem (A staging reused) ----
        __syncthreads();
        float* red = reinterpret_cast<float*>(smem + SM_A);
        if (khalf == 1) {
            int s = (wid - 4) * 32 + lane;
#pragma unroll
            for (int g = 0; g < 3; g++)
#pragma unroll
                for (int mf = 0; mf < 2; mf++)
#pragma unroll
                    for (int e = 0; e < 4; e++)
                        red[(g * 8 + mf * 4 + e) * 128 + s] = acc[g][mf][e];
        }
        __syncthreads();

        if (khalf == 0) {
            int s = wid * 32 + lane;
#pragma unroll
            for (int g = 0; g < 3; g++)
#pragma unroll
                for (int mf = 0; mf < 2; mf++)
#pragma unroll
                    for (int e = 0; e < 4; e++)
                        acc[g][mf][e] += red[(g * 8 + mf * 4 + e) * 128 + s];

            __nv_bfloat16* __restrict__ hdst_hi = g_h_hi[tpar ^ 1];
            __nv_bfloat16* __restrict__ hdst_lo = g_h_lo[tpar ^ 1];
#pragma unroll
            for (int i = 0; i < 4; i++) {           // row gr + i*8
                const int mf = i >> 1, dp = (i & 1) * 2;
                float zf0 = acc[0][mf][dp + 0] + bf0, zf1 = acc[0][mf][dp + 1] + bf1;
                float zg0 = acc[1][mf][dp + 0] + bg0, zg1 = acc[1][mf][dp + 1] + bg1;
                float zo0 = acc[2][mf][dp + 0] + bo0, zo1 = acc[2][mf][dp + 1] + bo1;
                float c0 = hsig(zf0) * c_reg[i * 2 + 0] + ig_reg[i * 2 + 0] * ftanh(zg0);
                float c1 = hsig(zf1) * c_reg[i * 2 + 1] + ig_reg[i * 2 + 1] * ftanh(zg1);
                c_reg[i * 2 + 0] = c0;
                c_reg[i * 2 + 1] = c1;
                float h0 = hsig(zo0) * ftanh(c0);
                float h1 = hsig(zo1) * ftanh(c1);
                int row = gr + i * 8;
                int idx = row * HH + uA;
                __nv_bfloat16 b0 = __float2bfloat16(h0);
                __nv_bfloat16 b1 = __float2bfloat16(h1);
                __nv_bfloat162 ph; ph.x = b0; ph.y = b1;
                *reinterpret_cast<__nv_bfloat162*>(&hdst_hi[idx]) = ph;
                __nv_bfloat162 pl;
                pl.x = __float2bfloat16(h0 - __bfloat162float(b0));
                pl.y = __float2bfloat16(h1 - __bfloat162float(b1));
                *reinterpret_cast<__nv_bfloat162*>(&hdst_lo[idx]) = pl;
                float2 ov = make_float2(h0, h1);
                *reinterpret_cast<float2*>(&out[(size_t)row * TT * HH + (size_t)t * HH + uA]) = ov;
            }
        }

        grid_bar_grp(mt, bar_t++);
    }
}

// ---------------- launcher ----------------
extern "C" void kernel_launch(void* const* d_in, const int* in_sizes, int n_in,
                              void* d_out, int out_size) {
    const float* x_dyn    = (const float*)d_in[0];
    const float* x_static = (const float*)d_in[1];
    const float* Wx       = (const float*)d_in[2];
    const float* Wh       = (const float*)d_in[3];
    const float* bias     = (const float*)d_in[4];
    const float* sk       = (const float*)d_in[5];
    const float* sb       = (const float*)d_in[6];
    float* out = (float*)d_out;

    cudaFuncSetAttribute(lstm_persist, cudaFuncAttributeMaxDynamicSharedMemorySize, SMEM_TOTAL);

    reset_bar<<<1, 256>>>();
    prep_weights<<<K3, 128>>>(Wx, Wh);
    prep_x<<<(BB * TT * DD + 127) / 128, 128>>>(x_dyn);
    lstm_persist<<<NBLK, 256, SMEM_TOTAL>>>(x_static, sk, sb, bias, out);
}